// round 15
// baseline (speedup 1.0000x reference)
#include <cuda_runtime.h>

// PairDistanceLoss: loss_i = (sum_{y=1} e^x)(sum_{y=0} e^{-x}) / (ni*(C-ni)); out = mean_i loss_i
// Shapes fixed: N=16384 rows, C=4096 cols. x: float32, y: int32, out: float32 scalar.
//
// R9 post-mortem: ticket (single-launch) = win; __ldcs = loss (DRAM 88->85.6%,
// evict-first hurts this streaming pattern on sm_103a). This kernel = ticket +
// plain loads: the verified-best halves of R8 and R9. R10 and R12 benches were
// broker/container failures (no compile or run output); resubmitting for a
// clean measurement of this exact configuration.

#define NROWS 16384
#define CCOLS 4096
#define BLK   256

// Scratch accumulator + ticket. Zero at module load; the last block of every
// launch resets both (atomicExch / atomicInc-wraparound), so every graph replay
// starts from zero. Allocation-free, deterministic work.
__device__ float        g_acc = 0.0f;
__device__ unsigned int g_ticket = 0u;

__device__ __forceinline__ void acc_elem(float xv, int yv,
                                         float& pos, float& neg, int& ni) {
    bool p = (yv != 0);
    float e = __expf(p ? xv : -xv);
    pos += p ? e : 0.0f;
    neg += p ? 0.0f : e;
    ni  += p ? 1 : 0;
}

__global__ __launch_bounds__(BLK, 1)
void pdl_row_kernel(const float* __restrict__ x, const int* __restrict__ y,
                    float* __restrict__ out) {
    const int row = blockIdx.x;
    const size_t base = (size_t)row * CCOLS;
    const float4* x4 = reinterpret_cast<const float4*>(x + base);
    const int4*   y4 = reinterpret_cast<const int4*>(y + base);

    const int tid = threadIdx.x;
    float pos = 0.0f, neg = 0.0f;
    int ni = 0;

    // C/4 = 1024 vec4 per row; 256 threads -> 4 fully-unrolled iterations.
    // Plain coalesced 16B loads (R8-verified 88% DRAM); 8 loads in flight per thread.
#pragma unroll
    for (int i = 0; i < 4; ++i) {
        const int idx = tid + i * BLK;   // vec4 index 0..1023
        float4 xv = x4[idx];
        int4   yv = y4[idx];
        acc_elem(xv.x, yv.x, pos, neg, ni);
        acc_elem(xv.y, yv.y, pos, neg, ni);
        acc_elem(xv.z, yv.z, pos, neg, ni);
        acc_elem(xv.w, yv.w, pos, neg, ni);
    }

    // Warp reduction
#pragma unroll
    for (int m = 16; m > 0; m >>= 1) {
        pos += __shfl_xor_sync(0xFFFFFFFFu, pos, m);
        neg += __shfl_xor_sync(0xFFFFFFFFu, neg, m);
        ni  += __shfl_xor_sync(0xFFFFFFFFu, ni,  m);
    }

    // Block reduction across 8 warps
    __shared__ float s_pos[8], s_neg[8];
    __shared__ int   s_ni[8];
    const int wid = tid >> 5, lid = tid & 31;
    if (lid == 0) { s_pos[wid] = pos; s_neg[wid] = neg; s_ni[wid] = ni; }
    __syncthreads();

    if (wid == 0 && lid == 0) {
        float p8 = 0.0f, n8 = 0.0f;
        int c8 = 0;
#pragma unroll
        for (int w = 0; w < 8; ++w) { p8 += s_pos[w]; n8 += s_neg[w]; c8 += s_ni[w]; }

        float denom = (float)c8 * (float)(CCOLS - c8);
        float contrib = p8 * n8 / denom * (1.0f / (float)NROWS);
        atomicAdd(&g_acc, contrib);

        // Order this block's accumulator add before its ticket increment.
        __threadfence();

        // atomicInc with val=NROWS-1 wraps to 0 when old==NROWS-1 -> ticket
        // self-resets every launch (graph-replay safe).
        unsigned int old = atomicInc(&g_ticket, NROWS - 1u);
        if (old == NROWS - 1u) {
            // All 16384 contributions are visible (each ticket inc is fenced
            // after its accumulator add). Read total and reset in one atomic.
            __threadfence();
            float total = atomicExch(&g_acc, 0.0f);
            out[0] = total;
        }
    }
}

extern "C" void kernel_launch(void* const* d_in, const int* in_sizes, int n_in,
                              void* d_out, int out_size) {
    const float* x = (const float*)d_in[0];
    const int*   y = (const int*)d_in[1];
    float* out = (float*)d_out;

    pdl_row_kernel<<<NROWS, BLK>>>(x, y, out);
}

// round 16
// speedup vs baseline: 1.0032x; 1.0032x over previous
#include <cuda_runtime.h>

// PairDistanceLoss: loss_i = (sum_{y=1} e^x)(sum_{y=0} e^{-x}) / (ni*(C-ni)); out = mean_i loss_i
// Shapes fixed: N=16384 rows, C=4096 cols. x: float32, y: int32, out: float32 scalar.
//
// R15 post-mortem: ticket tail (fence + atomicInc return-wait in warp 0 while the
// CTA holds its slot) costs ~13% residency -> DRAM 88->85%. NOT the load flavor.
// R16: 4 rows per block (grid 4096) amortizes the tail 4x; body/tail ratio
// restores residency while keeping the single-launch ticket (no init kernel).

#define NROWS 16384
#define CCOLS 4096
#define BLK   256
#define RPB   4                      // rows per block
#define GRID  (NROWS / RPB)          // 4096 blocks

// Scratch accumulator + ticket. Zero at module load; the last block of every
// launch resets both (atomicExch / atomicInc-wraparound) -> graph-replay safe.
__device__ float        g_acc = 0.0f;
__device__ unsigned int g_ticket = 0u;

__device__ __forceinline__ void acc_elem(float xv, int yv,
                                         float& pos, float& neg, int& ni) {
    bool p = (yv != 0);
    float e = __expf(p ? xv : -xv);
    pos += p ? e : 0.0f;
    neg += p ? 0.0f : e;
    ni  += p ? 1 : 0;
}

__global__ __launch_bounds__(BLK, 1)
void pdl_row_kernel(const float* __restrict__ x, const int* __restrict__ y,
                    float* __restrict__ out) {
    const int tid = threadIdx.x;
    const int wid = tid >> 5, lid = tid & 31;

    __shared__ float s_pos[8], s_neg[8];
    __shared__ int   s_ni[8];

    float block_sum = 0.0f;          // only meaningful in thread 0

    // 4 consecutive rows per block: 128KB contiguous stream per block.
#pragma unroll
    for (int j = 0; j < RPB; ++j) {
        const int row = blockIdx.x * RPB + j;
        const size_t base = (size_t)row * CCOLS;
        const float4* x4 = reinterpret_cast<const float4*>(x + base);
        const int4*   y4 = reinterpret_cast<const int4*>(y + base);

        float pos = 0.0f, neg = 0.0f;
        int ni = 0;

        // C/4 = 1024 vec4 per row; 256 threads -> 4 unrolled iters.
        // Plain coalesced 16B loads (R8-verified); 8 loads in flight per thread.
#pragma unroll
        for (int i = 0; i < 4; ++i) {
            const int idx = tid + i * BLK;
            float4 xv = x4[idx];
            int4   yv = y4[idx];
            acc_elem(xv.x, yv.x, pos, neg, ni);
            acc_elem(xv.y, yv.y, pos, neg, ni);
            acc_elem(xv.z, yv.z, pos, neg, ni);
            acc_elem(xv.w, yv.w, pos, neg, ni);
        }

        // Warp reduction
#pragma unroll
        for (int m = 16; m > 0; m >>= 1) {
            pos += __shfl_xor_sync(0xFFFFFFFFu, pos, m);
            neg += __shfl_xor_sync(0xFFFFFFFFu, neg, m);
            ni  += __shfl_xor_sync(0xFFFFFFFFu, ni,  m);
        }

        if (lid == 0) { s_pos[wid] = pos; s_neg[wid] = neg; s_ni[wid] = ni; }
        __syncthreads();

        if (tid == 0) {
            float p8 = 0.0f, n8 = 0.0f;
            int c8 = 0;
#pragma unroll
            for (int w = 0; w < 8; ++w) { p8 += s_pos[w]; n8 += s_neg[w]; c8 += s_ni[w]; }
            float denom = (float)c8 * (float)(CCOLS - c8);
            block_sum += p8 * n8 / denom;
        }
        __syncthreads();             // protect smem reuse by next row
    }

    // Amortized tail: ONE fence+ticket sequence per 4 rows.
    if (tid == 0) {
        atomicAdd(&g_acc, block_sum * (1.0f / (float)NROWS));  // RED (no return)
        __threadfence();             // order the add before the ticket inc

        unsigned int old = atomicInc(&g_ticket, GRID - 1u);    // wraps -> self-reset
        if (old == GRID - 1u) {
            __threadfence();
            float total = atomicExch(&g_acc, 0.0f);            // read + reset in one op
            out[0] = total;
        }
    }
}

extern "C" void kernel_launch(void* const* d_in, const int* in_sizes, int n_in,
                              void* d_out, int out_size) {
    const float* x = (const float*)d_in[0];
    const int*   y = (const int*)d_in[1];
    float* out = (float*)d_out;

    pdl_row_kernel<<<GRID, BLK>>>(x, y, out);
}